// round 11
// baseline (speedup 1.0000x reference)
#include <cuda_runtime.h>
#include <cuda_fp16.h>
#include <cstdint>
#include <math.h>

#define BB 8
#define SS 512
#define DD 256
#define NPAIRS (SS * (SS - 1) / 2)   // 130816
#define TILE 128
#define NT (SS / TILE)               // 4
#define NTRI (NT * (NT + 1) / 2)     // 10 lower-tri 128x128 tiles per batch
#define KC 64                        // K per smem chunk (128B rows)
#define NCH (DD / KC)                // 4

// ---- device globals (no cudaMalloc allowed) ----
__device__ float g_norms[BB * SS];
__device__ __align__(16) __half g_h[BB * SS * DD];   // fp16(x), 2MB

// tile LUT: (ti<<4)|tj for the 10 lower-tri 128-tiles
__device__ const uint8_t c_tij[NTRI] = {
    0x00, 0x10, 0x11, 0x20, 0x21, 0x22, 0x30, 0x31, 0x32, 0x33
};

// ---------------------------------------------------------------------------
__device__ __forceinline__ uint32_t smem_u32(const void* p) {
    uint32_t a;
    asm("{ .reg .u64 t; cvta.to.shared.u64 t, %1; cvt.u32.u64 %0, t; }" : "=r"(a) : "l"(p));
    return a;
}
__device__ __forceinline__ void cp_async16(uint32_t dst, const void* src) {
    asm volatile("cp.async.cg.shared.global [%0], [%1], 16;" :: "r"(dst), "l"(src) : "memory");
}
__device__ __forceinline__ void cp_commit() { asm volatile("cp.async.commit_group;" ::: "memory"); }
__device__ __forceinline__ void ldm_x4(uint32_t& r0, uint32_t& r1, uint32_t& r2, uint32_t& r3,
                                       uint32_t addr) {
    asm volatile("ldmatrix.sync.aligned.m8n8.x4.shared.b16 {%0,%1,%2,%3}, [%4];"
                 : "=r"(r0), "=r"(r1), "=r"(r2), "=r"(r3) : "r"(addr));
}
__device__ __forceinline__ void mma_f16(float* d, const uint32_t* a, const uint32_t* bfr) {
    asm volatile(
        "mma.sync.aligned.m16n8k16.row.col.f32.f16.f16.f32 "
        "{%0,%1,%2,%3}, {%4,%5,%6,%7}, {%8,%9}, {%0,%1,%2,%3};"
        : "+f"(d[0]), "+f"(d[1]), "+f"(d[2]), "+f"(d[3])
        : "r"(a[0]), "r"(a[1]), "r"(a[2]), "r"(a[3]), "r"(bfr[0]), "r"(bfr[1]));
}
__device__ __forceinline__ float sqrt_approx(float v) {
    float r;
    asm("sqrt.approx.f32 %0, %1;" : "=f"(r) : "f"(v));
    return r;
}

// ---------------------------------------------------------------------------
// Kernel 1: per-row norms (exact fp32) + fp16 conversion. One warp per row.
// ---------------------------------------------------------------------------
__global__ __launch_bounds__(256) void prep_kernel(const float* __restrict__ x) {
    int row = blockIdx.x * 8 + (threadIdx.x >> 5);
    int lane = threadIdx.x & 31;
    if (row >= BB * SS) return;
    const float4* x4 = reinterpret_cast<const float4*>(x) + (size_t)row * (DD / 4);
    float4 a = x4[lane];
    float4 c = x4[lane + 32];
    float s = a.x * a.x + a.y * a.y + a.z * a.z + a.w * a.w
            + c.x * c.x + c.y * c.y + c.z * c.z + c.w * c.w;
#pragma unroll
    for (int o = 16; o; o >>= 1) s += __shfl_xor_sync(0xFFFFFFFFu, s, o);
    if (lane == 0) g_norms[row] = s;

    size_t base = (size_t)row * DD;
#pragma unroll
    for (int g = 0; g < 2; ++g) {
        float4 v = g ? c : a;
        __half2 h0 = __floats2half2_rn(v.x, v.y);
        __half2 h1 = __floats2half2_rn(v.z, v.w);
        uint2 hv = make_uint2(*(uint32_t*)&h0, *(uint32_t*)&h1);
        *reinterpret_cast<uint2*>(g_h + base + g * 128 + lane * 4) = hv;
    }
}

// ---------------------------------------------------------------------------
// Kernel 2 (R4 replica, K=256): 128x128 Gram tile per CTA, 8 warps
// (2m x 4n, warp tile 64x32 -> 16 HMMA per 6 LDSM, 16 indep chains).
// K=256 in 4 chunks of 64 (128B rows, XOR-16B swizzle), QUAD-buffered:
// all 4 cp.async groups issued up front, progressive wait_group.
// fp32-accumulate mma.sync; diag tiles alias B -> A (skip 50% loads).
// smem: norms 1KB + 4 x (A 16KB + B 16KB) = 129.5KB -> 1 CTA/SM.
// ---------------------------------------------------------------------------
#define SM_NORM 1024
#define CHUNK_BYTES 32768            // A 16KB + B 16KB
#define SMEM_TOTAL (SM_NORM + NCH * CHUNK_BYTES)

__global__ __launch_bounds__(256) void dist_kernel(float* __restrict__ out) {
    extern __shared__ char smem[];
    uint32_t sbase = smem_u32(smem);
    int tid = threadIdx.x;
    int lane = tid & 31;
    int wid = tid >> 5;
    int wm = wid >> 2;   // 0..1 -> m offset 64*wm
    int wn = wid & 3;    // 0..3 -> n offset 32*wn

    int b = blockIdx.y;
    uint32_t tij = c_tij[blockIdx.x];
    int ti = tij >> 4, tj = tij & 15;
    bool diag = (ti == tj);

    // ---- issue all 4 chunk loads up front (separate commit groups) ----
    int rr = tid >> 3, cc = tid & 7;   // rr: 0..31 (+32q), cc: 16B slot in 128B row
    const __half* pAg = g_h + ((size_t)(b * SS + ti * TILE) + rr) * DD + cc * 8;
    const __half* pBg = g_h + ((size_t)(b * SS + tj * TILE) + rr) * DD + cc * 8;
    uint32_t swL = (cc ^ (rr & 7)) * 16;
    uint32_t dA = sbase + SM_NORM + rr * 128 + swL;
#pragma unroll
    for (int ch = 0; ch < NCH; ++ch) {
        uint32_t bo = ch * CHUNK_BYTES;
        const __half* sa = pAg + ch * KC;
        const __half* sb = pBg + ch * KC;
#pragma unroll
        for (int q = 0; q < 4; ++q) {   // rows rr + 32q
            cp_async16(dA + bo + q * 4096, sa + (size_t)q * 32 * DD);
            if (!diag) cp_async16(dA + bo + 16384 + q * 4096, sb + (size_t)q * 32 * DD);
        }
        cp_commit();
    }

    // ---- stage norms (overlaps with cp.async) ----
    float* si = reinterpret_cast<float*>(smem);          // rows (i)
    float* sjn = reinterpret_cast<float*>(smem + 512);   // cols (j)
    if (tid < 128) si[tid] = g_norms[b * SS + ti * TILE + tid];
    else sjn[tid - 128] = g_norms[b * SS + tj * TILE + (tid - 128)];

    // ---- per-lane ldmatrix addressing (128B rows, 8 x 16B slots) ----
    int rA = lane & 15;
    int kselA = (lane >> 4) & 1;
    int rB = (lane & 7) | ((lane >> 1) & 8);
    int kselB = (lane >> 3) & 1;
    uint32_t aRow = sbase + SM_NORM + (wm * 64 + rA) * 128;
    uint32_t bRow = sbase + SM_NORM + (diag ? 0 : 16384) + (wn * 32 + rB) * 128;
    uint32_t swA[4], swB[4];
#pragma unroll
    for (int ks = 0; ks < 4; ++ks) {
        swA[ks] = ((ks * 2 + kselA) ^ (rA & 7)) * 16;
        swB[ks] = ((ks * 2 + kselB) ^ (rB & 7)) * 16;
    }

    float acc[4][4][4];
#pragma unroll
    for (int mt = 0; mt < 4; ++mt)
#pragma unroll
        for (int nt = 0; nt < 4; ++nt)
#pragma unroll
            for (int e = 0; e < 4; ++e) acc[mt][nt][e] = 0.0f;

    // ---- mainloop: 4 chunks x 4 ks, progressive waits, no buffer reuse ----
#pragma unroll
    for (int ch = 0; ch < NCH; ++ch) {
        if (ch == 0) asm volatile("cp.async.wait_group 3;" ::: "memory");
        else if (ch == 1) asm volatile("cp.async.wait_group 2;" ::: "memory");
        else if (ch == 2) asm volatile("cp.async.wait_group 1;" ::: "memory");
        else asm volatile("cp.async.wait_group 0;" ::: "memory");
        __syncthreads();

        uint32_t bo = ch * CHUNK_BYTES;
#pragma unroll
        for (int ks = 0; ks < 4; ++ks) {
            uint32_t afr[4][4], bfr[2][4];
#pragma unroll
            for (int mt = 0; mt < 4; ++mt)
                ldm_x4(afr[mt][0], afr[mt][1], afr[mt][2], afr[mt][3],
                       aRow + bo + mt * 2048 + swA[ks]);
#pragma unroll
            for (int nh = 0; nh < 2; ++nh)
                ldm_x4(bfr[nh][0], bfr[nh][1], bfr[nh][2], bfr[nh][3],
                       bRow + bo + nh * 2048 + swB[ks]);
#pragma unroll
            for (int mt = 0; mt < 4; ++mt) {
#pragma unroll
                for (int nt = 0; nt < 4; ++nt) {
                    uint32_t bb2[2] = { bfr[nt >> 1][(nt & 1) * 2],
                                        bfr[nt >> 1][(nt & 1) * 2 + 1] };
                    mma_f16(acc[mt][nt], afr[mt], bb2);
                }
            }
        }
    }

    // ---- epilogue ----
    int lr = lane >> 2;            // 0..7
    int lc = 2 * (lane & 3);       // 0,2,4,6
    float* ob = out + (size_t)b * NPAIRS;
#pragma unroll
    for (int mt = 0; mt < 4; ++mt) {
        int r0 = wm * 64 + mt * 16 + lr;
        int i0 = ti * TILE + r0;
        int i1 = i0 + 8;
        float n0 = si[r0], n1 = si[r0 + 8];
        int base0 = i0 * (i0 - 1) / 2;
        int base1 = i1 * (i1 - 1) / 2;
#pragma unroll
        for (int nt = 0; nt < 4; ++nt) {
            int col = wn * 32 + nt * 8 + lc;
            int j = tj * TILE + col;
            float njc0 = sjn[col], njc1 = sjn[col + 1];
            float* c = acc[mt][nt];
            if (j < i0)     ob[base0 + j]     = sqrt_approx(fmaxf(n0 + njc0 - 2.0f * c[0], 1e-7f));
            if (j + 1 < i0) ob[base0 + j + 1] = sqrt_approx(fmaxf(n0 + njc1 - 2.0f * c[1], 1e-7f));
            if (j < i1)     ob[base1 + j]     = sqrt_approx(fmaxf(n1 + njc0 - 2.0f * c[2], 1e-7f));
            if (j + 1 < i1) ob[base1 + j + 1] = sqrt_approx(fmaxf(n1 + njc1 - 2.0f * c[3], 1e-7f));
        }
    }
}

// ---------------------------------------------------------------------------
extern "C" void kernel_launch(void* const* d_in, const int* in_sizes, int n_in,
                              void* d_out, int out_size) {
    const float* x = (const float*)d_in[0];
    float* out = (float*)d_out;

    static bool attr_done = false;
    if (!attr_done) {
        cudaFuncSetAttribute(dist_kernel, cudaFuncAttributeMaxDynamicSharedMemorySize,
                             SMEM_TOTAL);
        attr_done = true;
    }

    prep_kernel<<<512, 256>>>(x);

    dim3 grid(NTRI, BB);
    dist_kernel<<<grid, 256, SMEM_TOTAL>>>(out);
}